// round 8
// baseline (speedup 1.0000x reference)
#include <cuda_runtime.h>
#include <cstdint>

// Twist2Mat (Rodrigues): twist [B,R,3] f32 -> rot [B,R,3,3] f32
// N = B*R = 8,388,608. Memory-bound: 384 MB streaming (96 read / 288 write).
//
// R1: strided per-thread stores -> 9x L1 wf amplification (166us).
// R2: block smem staging, coalesced I/O (66.3us, DRAM 68%).
// R3: warp-private tiles + __ldcs/__stcs (63.9us, DRAM 70%).
// R4: 1-deep register prefetch — neutral.
// R5: batched read MLP (3 LDG.128/lane) — neutral (L1tex queue-capped).
// R6: TMA bulk stores — best in-profile (58.7us, DRAM 73.8%).
// R7: TMA bulk LOADS too (cp.async.bulk global->shared + per-warp mbarrier):
//     both streams fully async, LDG leaves the L1tex/LSU path entirely.

#ifndef TPB
#define TPB 256
#endif
#define WARPS (TPB / 32)
#define TILES 4            // 32-element tiles per warp => 128 elems/warp

__device__ __forceinline__ void rodrigues9(float x, float y, float z, float* __restrict__ r)
{
    float n2    = fmaf(x, x, fmaf(y, y, z * z));
    float theta = fmaxf(sqrtf(n2), 1e-5f);
    float inv   = __fdividef(1.0f, theta);
    float a0 = x * inv, a1 = y * inv, a2 = z * inv;

    float s, c;
    __sincosf(theta, &s, &c);
    float k = 1.0f - c;

    // R = c*I + s*[a]_x + k*(a a^T)
    float ka0 = k * a0, ka1 = k * a1;
    float sa0 = s * a0, sa1 = s * a1, sa2 = s * a2;

    r[0] = fmaf(ka0, a0, c);
    r[1] = fmaf(ka0, a1, -sa2);
    r[2] = fmaf(ka0, a2,  sa1);
    r[3] = fmaf(ka0, a1,  sa2);
    r[4] = fmaf(ka1, a1, c);
    r[5] = fmaf(ka1, a2, -sa0);
    r[6] = fmaf(ka0, a2, -sa1);
    r[7] = fmaf(ka1, a2,  sa0);
    r[8] = fmaf(k * a2, a2, c);
}

__global__ __launch_bounds__(TPB)
void twist2mat_tma2_kernel(const float4* __restrict__ in4,
                           float4* __restrict__ out4,
                           int n_elems)
{
    __shared__ __align__(16) float s_in [WARPS][TILES * 96];     // 1536 B / warp
    __shared__ __align__(16) float s_out[WARPS][2][288];         // 2x1152 B / warp
    __shared__ __align__(8)  unsigned long long s_mbar[WARPS];

    const int lane = threadIdx.x & 31;
    const int wrp  = threadIdx.x >> 5;
    const long long wstart = ((long long)blockIdx.x * WARPS + wrp) * (32 * TILES);
    if (wstart >= n_elems) return;

    const float4* gin  = in4  + wstart / 4 * 3;   // wstart*3/4 (1536B-aligned)
    float4*       gout = out4 + wstart / 4 * 9;   // wstart*9/4

    const bool warp_full = (wstart + 32 * TILES <= n_elems);

    if (warp_full) {
        // ---- TMA bulk load: 1536 B global -> shared, per-warp mbarrier ----
        const uint32_t mbar = (uint32_t)__cvta_generic_to_shared(&s_mbar[wrp]);
        if (lane == 0) {
            asm volatile("mbarrier.init.shared.b64 [%0], %1;" :: "r"(mbar), "r"(1) : "memory");
            asm volatile("fence.proxy.async.shared::cta;" ::: "memory");
            asm volatile("mbarrier.arrive.expect_tx.shared.b64 _, [%0], %1;"
                         :: "r"(mbar), "r"(1536) : "memory");
            uint32_t dst = (uint32_t)__cvta_generic_to_shared(s_in[wrp]);
            asm volatile(
                "cp.async.bulk.shared::cta.global.mbarrier::complete_tx::bytes [%0], [%1], %2, [%3];"
                :: "r"(dst), "l"((const void*)gin), "n"(1536), "r"(mbar) : "memory");
        }
        __syncwarp();   // init+issue visible before any lane polls

        // ---- wait (phase 0), acquire so LDS below sees the bulk data ----
        {
            uint32_t done;
            asm volatile(
                "{\n\t.reg .pred p;\n\t"
                "mbarrier.try_wait.parity.acquire.cta.shared::cta.b64 p, [%1], %2;\n\t"
                "selp.b32 %0, 1, 0, p;\n\t}"
                : "=r"(done) : "r"(mbar), "r"(0) : "memory");
            if (!done) {
                asm volatile(
                    "{\n\t.reg .pred P1;\n\t"
                    "WL_%=:\n\t"
                    "mbarrier.try_wait.parity.acquire.cta.shared::cta.b64 P1, [%0], %1, 0x989680;\n\t"
                    "@P1 bra.uni WD_%=;\n\t"
                    "bra.uni WL_%=;\n\t"
                    "WD_%=:\n\t}"
                    :: "r"(mbar), "r"(0) : "memory");
            }
        }

#pragma unroll
        for (int t = 0; t < TILES; t++) {
            // Buffer (t&1) is reusable once the bulk store from tile t-2 has
            // finished READING it; groups retire in order.
            if (t >= 2) {
                if (lane == 0)
                    asm volatile("cp.async.bulk.wait_group.read 1;" ::: "memory");
                __syncwarp();
            }

            // ---- compute: 1 element per lane (stride-3 LDS, stride-9 STS) ----
            {
                const float* si = s_in[wrp] + t * 96;
                float x = si[3 * lane + 0];
                float y = si[3 * lane + 1];
                float z = si[3 * lane + 2];
                float r[9];
                rodrigues9(x, y, z, r);
                float* so = s_out[wrp][t & 1];
#pragma unroll
                for (int i = 0; i < 9; i++)
                    so[9 * lane + i] = r[i];
            }
            __syncwarp();

            // ---- TMA bulk store: 1152 contiguous bytes, async proxy ----
            if (lane == 0) {
                asm volatile("fence.proxy.async.shared::cta;" ::: "memory");
                uint32_t src = (uint32_t)__cvta_generic_to_shared(s_out[wrp][t & 1]);
                void* dst = (void*)(gout + t * 72);
                asm volatile(
                    "cp.async.bulk.global.shared::cta.bulk_group [%0], [%1], %2;"
                    :: "l"(dst), "r"(src), "n"(1152) : "memory");
                asm volatile("cp.async.bulk.commit_group;" ::: "memory");
            }
        }
        // Drain all bulk stores before this warp exits.
        if (lane == 0)
            asm volatile("cp.async.bulk.wait_group 0;" ::: "memory");
    } else {
        // ---- scalar-safe tail path (not hit for this shape) ----
        {
            const float* gf = (const float*)gin;
            int vf = (int)(n_elems - wstart) * 3;
            for (int i = lane; i < TILES * 96; i += 32)
                s_in[wrp][i] = (i < vf) ? gf[i] : 1.0f;
        }
        __syncwarp();
        for (int t = 0; t < TILES; t++) {
            const long long tbase = wstart + 32LL * t;
            if (tbase >= n_elems) break;
            const float* si = s_in[wrp] + t * 96;
            float r[9];
            rodrigues9(si[3 * lane], si[3 * lane + 1], si[3 * lane + 2], r);
            float* so = s_out[wrp][0];
#pragma unroll
            for (int i = 0; i < 9; i++)
                so[9 * lane + i] = r[i];
            __syncwarp();
            float* gf = (float*)(gout + t * 72);
            long long ve = n_elems - tbase;
            int vf = (int)((ve < 32 ? ve : 32) * 9);
            for (int i = lane; i < vf; i += 32)
                gf[i] = so[i];
            __syncwarp();
        }
    }
}

extern "C" void kernel_launch(void* const* d_in, const int* in_sizes, int n_in,
                              void* d_out, int out_size)
{
    const float* twist = (const float*)d_in[0];
    float* out = (float*)d_out;

    int n_elems = in_sizes[0] / 3;                       // 8,388,608
    long long per_block = (long long)WARPS * 32 * TILES; // 1024
    int blocks = (int)((n_elems + per_block - 1) / per_block);

    twist2mat_tma2_kernel<<<blocks, TPB>>>((const float4*)twist, (float4*)out, n_elems);
}

// round 9
// speedup vs baseline: 1.0151x; 1.0151x over previous
#include <cuda_runtime.h>
#include <cstdint>

// Twist2Mat (Rodrigues): twist [B,R,3] f32 -> rot [B,R,3,3] f32
// N = B*R = 8,388,608. Memory-bound: 384 MB streaming (96 read / 288 write).
//
// R1: strided per-thread stores -> 9x L1 wf amplification (166us).
// R2: block smem staging, coalesced I/O (66.3us, DRAM 68%).
// R3: warp-private tiles + __ldcs/__stcs (63.9us, DRAM 70%).
// R4/R5: prefetch + read-MLP batching — neutral (reads not the constraint).
// R6: TMA bulk stores — best (harness 63.9us, profile 58.7us, DRAM 73.8%).
// R7: TMA bulk loads — neutral-negative; reverted to LDG loads.
// R9: R6 + paired 2304B bulk stores (2 TMA ops/warp, not 4) and no mid-loop
//     wait_group: each store buffer written once, drained only at warp exit.
//     We are ~95% of the LTS fabric ceiling (~6.5-6.9 TB/s for all traffic);
//     this trims per-op overhead, not bandwidth.

#ifndef TPB
#define TPB 256
#endif
#define WARPS (TPB / 32)
#define TILES 4            // 32-element tiles per warp => 128 elems/warp

__device__ __forceinline__ void rodrigues9(float x, float y, float z, float* __restrict__ r)
{
    float n2    = fmaf(x, x, fmaf(y, y, z * z));
    float theta = fmaxf(sqrtf(n2), 1e-5f);
    float inv   = __fdividef(1.0f, theta);
    float a0 = x * inv, a1 = y * inv, a2 = z * inv;

    float s, c;
    __sincosf(theta, &s, &c);
    float k = 1.0f - c;

    // R = c*I + s*[a]_x + k*(a a^T)
    float ka0 = k * a0, ka1 = k * a1;
    float sa0 = s * a0, sa1 = s * a1, sa2 = s * a2;

    r[0] = fmaf(ka0, a0, c);
    r[1] = fmaf(ka0, a1, -sa2);
    r[2] = fmaf(ka0, a2,  sa1);
    r[3] = fmaf(ka0, a1,  sa2);
    r[4] = fmaf(ka1, a1, c);
    r[5] = fmaf(ka1, a2, -sa0);
    r[6] = fmaf(ka0, a2, -sa1);
    r[7] = fmaf(ka1, a2,  sa0);
    r[8] = fmaf(k * a2, a2, c);
}

__global__ __launch_bounds__(TPB)
void twist2mat_pair_kernel(const float4* __restrict__ in4,
                           float4* __restrict__ out4,
                           int n_elems)
{
    __shared__ float s_in [WARPS][TILES * 96];                 // 1536 B / warp
    __shared__ __align__(16) float s_out[WARPS][2][576];       // 2 x 2304 B / warp

    const int lane = threadIdx.x & 31;
    const int wrp  = threadIdx.x >> 5;
    const long long wstart = ((long long)blockIdx.x * WARPS + wrp) * (32 * TILES);
    if (wstart >= n_elems) return;

    const float4* gin  = in4  + wstart / 4 * 3;   // wstart*3/4
    float4*       gout = out4 + wstart / 4 * 9;   // wstart*9/4

    const bool warp_full = (wstart + 32 * TILES <= n_elems);

    // ---- batched coalesced load: 96 float4 per warp (3 per lane) ----
    if (warp_full) {
        float4* s = (float4*)s_in[wrp];
#pragma unroll
        for (int j = 0; j < 3; j++)
            s[lane + 32 * j] = __ldcs(gin + lane + 32 * j);
    } else {
        const float* gf = (const float*)gin;
        int vf = (int)(n_elems - wstart) * 3;
        for (int i = lane; i < TILES * 96; i += 32)
            s_in[wrp][i] = (i < vf) ? gf[i] : 1.0f;   // pad, never stored
    }
    __syncwarp();

    if (warp_full) {
#pragma unroll
        for (int p = 0; p < TILES / 2; p++) {
            // ---- compute two tiles into one contiguous 2304B buffer ----
            float* sop = s_out[wrp][p];
#pragma unroll
            for (int sub = 0; sub < 2; sub++) {
                const int t = 2 * p + sub;
                const float* si = s_in[wrp] + t * 96;
                float x = si[3 * lane + 0];
                float y = si[3 * lane + 1];
                float z = si[3 * lane + 2];
                float r[9];
                rodrigues9(x, y, z, r);
                float* so = sop + sub * 288;
#pragma unroll
                for (int i = 0; i < 9; i++)
                    so[9 * lane + i] = r[i];          // stride-9 STS: conflict-free
            }
            __syncwarp();

            // ---- one TMA bulk store per pair: 2304 contiguous bytes ----
            if (lane == 0) {
                asm volatile("fence.proxy.async.shared::cta;" ::: "memory");
                uint32_t src = (uint32_t)__cvta_generic_to_shared(sop);
                void* dst = (void*)(gout + p * 144);
                asm volatile(
                    "cp.async.bulk.global.shared::cta.bulk_group [%0], [%1], %2;"
                    :: "l"(dst), "r"(src), "n"(2304) : "memory");
                asm volatile("cp.async.bulk.commit_group;" ::: "memory");
            }
            // no mid-loop wait: each buffer is written exactly once
        }
        // Drain bulk stores before warp exit (smem may be reallocated).
        if (lane == 0)
            asm volatile("cp.async.bulk.wait_group 0;" ::: "memory");
    } else {
        // ---- scalar-safe tail path (not hit for this shape) ----
        for (int t = 0; t < TILES; t++) {
            const long long tbase = wstart + 32LL * t;
            if (tbase >= n_elems) break;
            const float* si = s_in[wrp] + t * 96;
            float r[9];
            rodrigues9(si[3 * lane], si[3 * lane + 1], si[3 * lane + 2], r);
            float* so = s_out[wrp][0];
#pragma unroll
            for (int i = 0; i < 9; i++)
                so[9 * lane + i] = r[i];
            __syncwarp();
            float* gf = (float*)(gout + t * 72);
            long long ve = n_elems - tbase;
            int vf = (int)((ve < 32 ? ve : 32) * 9);
            for (int i = lane; i < vf; i += 32)
                gf[i] = so[i];
            __syncwarp();
        }
    }
}

extern "C" void kernel_launch(void* const* d_in, const int* in_sizes, int n_in,
                              void* d_out, int out_size)
{
    const float* twist = (const float*)d_in[0];
    float* out = (float*)d_out;

    int n_elems = in_sizes[0] / 3;                       // 8,388,608
    long long per_block = (long long)WARPS * 32 * TILES; // 1024
    int blocks = (int)((n_elems + per_block - 1) / per_block);

    twist2mat_pair_kernel<<<blocks, TPB>>>((const float4*)twist, (float4*)out, n_elems);
}